// round 13
// baseline (speedup 1.0000x reference)
#include <cuda_runtime.h>
#include <cstdint>

#define W 131072
#define J 21
#define NB 20
#define BLOCK 256
#define GRID 2048
#define WPB (BLOCK / 32)
#define NWARP (GRID * WPB)                 // 16384 warps
#define CHUNK (W / NWARP)                  // 8 frames per warp (exact)
#define NSTEP (CHUNK / 2)                  // 4 steps of 2 frames

// weights folded with denominators
#define C_PROJ   (1.0f / 42.0f)
#define C_BONE   (1.0f / 20.0f)
#define C_SMOOTH (0.5f / 63.0f)
#define C_LIFT   (0.1f / 63.0f)

#define FULL 0xFFFFFFFFu

__device__ double g_acc;           // zero at load; last block resets each call
__device__ unsigned int g_count;   // wraps to 0 via atomicInc

__global__ __launch_bounds__(BLOCK, 5)
void loss_kernel(const float* __restrict__ pose,   // [(W+1),3,J]
                 const float* __restrict__ cam,    // [W,2,3]
                 const float* __restrict__ p2d,    // [W,2,J]
                 const float* __restrict__ blen,   // [NB]
                 const float* __restrict__ lift,   // [W,3,NB]
                 const int*   __restrict__ bc,     // [NB,2]
                 const int*   __restrict__ lbc,    // [NB,2]
                 float* __restrict__ out)
{
    const int tid  = threadIdx.x;
    const int lane = tid & 31;
    const int wid  = tid >> 5;
    const int gw   = blockIdx.x * WPB + wid;
    const int f0   = gw * CHUNK;

    const bool jok = lane < J;
    const bool bok = lane < NB;

    int ch = 0, pa = 0, lch = 0, lpa = 0;
    float bl = 0.0f;
    if (bok) {
        ch  = bc[2 * lane];
        pa  = bc[2 * lane + 1];
        lch = lbc[2 * lane];
        lpa = lbc[2 * lane + 1];
        bl  = blen[lane];
    }
    // warp-uniform structure checks (generic fallbacks preserved)
    const bool same_conn = __all_sync(FULL, !bok || (lch == ch && lpa == pa));
    const bool chain     = __all_sync(FULL, !bok || (ch == lane + 1 && pa == lane));

    float acc = 0.0f;

    // double-buffered per-step register sets (fully unrolled -> registers)
    float X1[2], Y1[2], Z1[2], X2[2], Y2[2], Z2[2];
    float QX1[2], QY1[2], QX2[2], QY2[2];
    float LX1[2], LY1[2], LZ1[2], LX2[2], LY2[2], LZ2[2];

    // ---- lead-in history: x0 = frame f0, xm = frame max(f0-1,0) ----
    const float* pA = pose + (size_t)f0 * 63;
    float x0 = jok ? pA[lane]          : 0.0f;
    float y0 = jok ? pA[J + lane]      : 0.0f;
    float z0 = jok ? pA[2 * J + lane]  : 0.0f;
    const float* pB = pose + (size_t)(f0 > 0 ? f0 - 1 : 0) * 63;
    float xm = jok ? pB[lane]          : 0.0f;
    float ym = jok ? pB[J + lane]      : 0.0f;
    float zm = jok ? pB[2 * J + lane]  : 0.0f;

    // ---- prologue: load step 0 into buffer 0 ----
    {
        const int w = f0;
        const float* pf1 = pose + (size_t)(w + 1) * 63;
        X1[0] = jok ? pf1[lane]         : 0.0f;
        Y1[0] = jok ? pf1[J + lane]     : 0.0f;
        Z1[0] = jok ? pf1[2 * J + lane] : 0.0f;
        const float* pf2 = pf1 + 63;
        X2[0] = jok ? pf2[lane]         : 0.0f;
        Y2[0] = jok ? pf2[J + lane]     : 0.0f;
        Z2[0] = jok ? pf2[2 * J + lane] : 0.0f;
        const float* qa = p2d + (size_t)w * 42;
        QX1[0] = jok ? qa[lane]     : 0.0f;
        QY1[0] = jok ? qa[J + lane] : 0.0f;
        QX2[0] = jok ? qa[42 + lane]     : 0.0f;
        QY2[0] = jok ? qa[42 + J + lane] : 0.0f;
        const float* la = lift + (size_t)w * 60;
        LX1[0] = bok ? la[lane]          : 0.0f;
        LY1[0] = bok ? la[NB + lane]     : 0.0f;
        LZ1[0] = bok ? la[2 * NB + lane] : 0.0f;
        LX2[0] = bok ? la[60 + lane]          : 0.0f;
        LY2[0] = bok ? la[60 + NB + lane]     : 0.0f;
        LZ2[0] = bok ? la[60 + 2 * NB + lane] : 0.0f;
    }

    // frame-0 bone term (done once, by the warp owning frame 0)
    if (f0 == 0) {
        float dx = __shfl_sync(FULL, x0, ch) - __shfl_sync(FULL, x0, pa);
        float dy = __shfl_sync(FULL, y0, ch) - __shfl_sync(FULL, y0, pa);
        float dz = __shfl_sync(FULL, z0, ch) - __shfl_sync(FULL, z0, pa);
        float len = dx * dx + dy * dy + dz * dz;
        float e = len - bl;
        if (bok) acc += C_BONE * e * e;
    }

    #pragma unroll
    for (int s = 0; s < NSTEP; s++) {
        const int cur = s & 1;
        const int nxt = cur ^ 1;
        const int w   = f0 + 2 * s;

        // ===== prefetch step s+1 (hidden behind this step's compute) =====
        if (s + 1 < NSTEP) {
            const int wn = w + 2;
            const float* pf1 = pose + (size_t)(wn + 1) * 63;
            X1[nxt] = jok ? pf1[lane]         : 0.0f;
            Y1[nxt] = jok ? pf1[J + lane]     : 0.0f;
            Z1[nxt] = jok ? pf1[2 * J + lane] : 0.0f;
            const float* pf2 = pf1 + 63;
            X2[nxt] = jok ? pf2[lane]         : 0.0f;
            Y2[nxt] = jok ? pf2[J + lane]     : 0.0f;
            Z2[nxt] = jok ? pf2[2 * J + lane] : 0.0f;
            const float* qa = p2d + (size_t)wn * 42;
            QX1[nxt] = jok ? qa[lane]     : 0.0f;
            QY1[nxt] = jok ? qa[J + lane] : 0.0f;
            QX2[nxt] = jok ? qa[42 + lane]     : 0.0f;
            QY2[nxt] = jok ? qa[42 + J + lane] : 0.0f;
            const float* la = lift + (size_t)wn * 60;
            LX1[nxt] = bok ? la[lane]          : 0.0f;
            LY1[nxt] = bok ? la[NB + lane]     : 0.0f;
            LZ1[nxt] = bok ? la[2 * NB + lane] : 0.0f;
            LX2[nxt] = bok ? la[60 + lane]          : 0.0f;
            LY2[nxt] = bok ? la[60 + NB + lane]     : 0.0f;
            LZ2[nxt] = bok ? la[60 + 2 * NB + lane] : 0.0f;
        }

        const float x1 = X1[cur], y1 = Y1[cur], z1 = Z1[cur];
        const float x2 = X2[cur], y2 = Y2[cur], z2 = Z2[cur];

        // ======== frame w ========
        {
            const float2* c = (const float2*)(cam + (size_t)w * 6);
            float2 c0 = c[0], c1 = c[1], c2 = c[2];
            float px = c0.x * x1 + c0.y * y1 + c1.x * z1 - QX1[cur];
            float py = c1.y * x1 + c2.x * y1 + c2.y * z1 - QY1[cur];
            if (jok) acc += C_PROJ * (px * px + py * py);

            if (w >= 1 || s > 0) {
                float a0 = x1 - 2.0f * x0 + xm;
                float a1 = y1 - 2.0f * y0 + ym;
                float a2 = z1 - 2.0f * z0 + zm;
                if (jok) acc += C_SMOOTH * (a0 * a0 + a1 * a1 + a2 * a2);
            }

            float bx, by, bz;
            if (chain) {
                bx = __shfl_down_sync(FULL, x1, 1) - x1;
                by = __shfl_down_sync(FULL, y1, 1) - y1;
                bz = __shfl_down_sync(FULL, z1, 1) - z1;
            } else {
                bx = __shfl_sync(FULL, x1, ch) - __shfl_sync(FULL, x1, pa);
                by = __shfl_sync(FULL, y1, ch) - __shfl_sync(FULL, y1, pa);
                bz = __shfl_sync(FULL, z1, ch) - __shfl_sync(FULL, z1, pa);
            }
            float len = bx * bx + by * by + bz * bz;
            float e = len - bl;
            if (bok) acc += C_BONE * e * e;

            float ux, uy, uz;
            if (same_conn) { ux = bx; uy = by; uz = bz; }
            else {
                ux = __shfl_sync(FULL, x1, lch) - __shfl_sync(FULL, x1, lpa);
                uy = __shfl_sync(FULL, y1, lch) - __shfl_sync(FULL, y1, lpa);
                uz = __shfl_sync(FULL, z1, lch) - __shfl_sync(FULL, z1, lpa);
            }
            float inv = bok ? (1.0f / sqrtf(ux * ux + uy * uy + uz * uz)) : 0.0f;
            float ex = LX1[cur] - ux * inv;
            float ey = LY1[cur] - uy * inv;
            float ez = LZ1[cur] - uz * inv;
            if (bok) acc += C_LIFT * (ex * ex + ey * ey + ez * ez);
        }

        // ======== frame w+1 ========
        {
            const float2* c = (const float2*)(cam + (size_t)(w + 1) * 6);
            float2 c0 = c[0], c1 = c[1], c2 = c[2];
            float px = c0.x * x2 + c0.y * y2 + c1.x * z2 - QX2[cur];
            float py = c1.y * x2 + c2.x * y2 + c2.y * z2 - QY2[cur];
            if (jok) acc += C_PROJ * (px * px + py * py);

            float a0 = x2 - 2.0f * x1 + x0;
            float a1 = y2 - 2.0f * y1 + y0;
            float a2 = z2 - 2.0f * z1 + z0;
            if (jok) acc += C_SMOOTH * (a0 * a0 + a1 * a1 + a2 * a2);

            float bx, by, bz;
            if (chain) {
                bx = __shfl_down_sync(FULL, x2, 1) - x2;
                by = __shfl_down_sync(FULL, y2, 1) - y2;
                bz = __shfl_down_sync(FULL, z2, 1) - z2;
            } else {
                bx = __shfl_sync(FULL, x2, ch) - __shfl_sync(FULL, x2, pa);
                by = __shfl_sync(FULL, y2, ch) - __shfl_sync(FULL, y2, pa);
                bz = __shfl_sync(FULL, z2, ch) - __shfl_sync(FULL, z2, pa);
            }
            float len = bx * bx + by * by + bz * bz;
            float e = len - bl;
            if (bok) acc += C_BONE * e * e;

            float ux, uy, uz;
            if (same_conn) { ux = bx; uy = by; uz = bz; }
            else {
                ux = __shfl_sync(FULL, x2, lch) - __shfl_sync(FULL, x2, lpa);
                uy = __shfl_sync(FULL, y2, lch) - __shfl_sync(FULL, y2, lpa);
                uz = __shfl_sync(FULL, z2, lch) - __shfl_sync(FULL, z2, lpa);
            }
            float inv = bok ? (1.0f / sqrtf(ux * ux + uy * uy + uz * uz)) : 0.0f;
            float ex = LX2[cur] - ux * inv;
            float ey = LY2[cur] - uy * inv;
            float ez = LZ2[cur] - uz * inv;
            if (bok) acc += C_LIFT * (ex * ex + ey * ey + ez * ez);
        }

        // rotate history: prev = pose[w+1], cur = pose[w+2]
        xm = x1; ym = y1; zm = z1;
        x0 = x2; y0 = y2; z0 = z2;
    }

    // ---- warp reduction ----
    #pragma unroll
    for (int off = 16; off > 0; off >>= 1)
        acc += __shfl_down_sync(FULL, acc, off);

    __shared__ float warp_sums[WPB];
    __shared__ bool  is_last;
    if (lane == 0) warp_sums[wid] = acc;
    __syncthreads();

    if (wid == 0) {
        float v = (lane < WPB) ? warp_sums[lane] : 0.0f;
        #pragma unroll
        for (int off = 4; off > 0; off >>= 1)
            v += __shfl_down_sync(FULL, v, off);
        if (lane == 0) {
            atomicAdd(&g_acc, (double)v);
            __threadfence();
            unsigned int ticket = atomicInc(&g_count, GRID - 1);
            is_last = (ticket == GRID - 1);
        }
    }
    __syncthreads();

    if (is_last && tid == 0) {
        __threadfence();
        out[0] = (float)g_acc;
        g_acc = 0.0;   // reset for next graph replay (g_count already wrapped)
        __threadfence();
    }
}

extern "C" void kernel_launch(void* const* d_in, const int* in_sizes, int n_in,
                              void* d_out, int out_size)
{
    const float* pose = (const float*)d_in[0];
    const float* cam  = (const float*)d_in[1];
    const float* p2d  = (const float*)d_in[2];
    const float* blen = (const float*)d_in[3];
    const float* lift = (const float*)d_in[4];
    const int*   bc   = (const int*)d_in[5];
    const int*   lbc  = (const int*)d_in[6];
    float* out = (float*)d_out;

    loss_kernel<<<GRID, BLOCK>>>(pose, cam, p2d, blen, lift, bc, lbc, out);
}